// round 15
// baseline (speedup 1.0000x reference)
#include <cuda_runtime.h>
#include <cuda_bf16.h>
#include <math.h>
#include <stdint.h>

typedef unsigned int u32; typedef unsigned long long u64;
typedef __nv_bfloat16 bf16;

#define Bb   2
#define Ss   1024
#define Tt   2048
#define Hh   1024
#define NHh  16
#define HDd  64
#define Ee   8
#define Ii   2048
#define NSLOT (Tt*2)

// ---- fp32 scratch ----
__device__ float g_xn[Tt*Hh];
__device__ float g_q [Tt*Hh];
__device__ float g_k [Tt*Hh];
__device__ float g_v [Tt*Hh];
__device__ float g_h [Tt*Hh];
__device__ float g_hn[Tt*Hh];
__device__ float g_y [NSLOT*Hh];
__device__ float g_t1[NSLOT*Ii];
__device__ int   g_topi[Tt*2];
__device__ float g_topw[Tt*2];
__device__ int   g_slot[Tt*2];
__device__ int   g_tok [NSLOT];
__device__ int   g_cnt [Ee];
__device__ int   g_off [Ee];
__device__ int   g_fill[Ee];

// ---- bf16 split activations (produced fused in upstream kernels) ----
__device__ __align__(16) bf16 g_xn_hi[Tt*Hh],  g_xn_lo[Tt*Hh];
__device__ __align__(16) bf16 g_hn_hi[Tt*Hh],  g_hn_lo[Tt*Hh];
__device__ __align__(16) bf16 g_ao_hi[Tt*Hh],  g_ao_lo[Tt*Hh];
__device__ __align__(16) bf16 g_act_hi[NSLOT*Ii], g_act_lo[NSLOT*Ii];

// ---------------- low-level helpers (plain-sm_103-legal) ----------------
__device__ __forceinline__ u32 sm2u(const void* p) {
    u32 a; asm("{ .reg .u64 t; cvta.to.shared.u64 t, %1; cvt.u32.u64 %0, t; }" : "=r"(a) : "l"(p)); return a;
}
__device__ __forceinline__ void cpa16(u32 dst, const void* src) {
    asm volatile("cp.async.cg.shared.global [%0], [%1], 16;" :: "r"(dst), "l"(src));
}
__device__ __forceinline__ void ldmx4(u32& r0, u32& r1, u32& r2, u32& r3, u32 a) {
    asm volatile("ldmatrix.sync.aligned.m8n8.x4.shared.b16 {%0,%1,%2,%3}, [%4];"
        : "=r"(r0), "=r"(r1), "=r"(r2), "=r"(r3) : "r"(a));
}
__device__ __forceinline__ void ldmx4t(u32& r0, u32& r1, u32& r2, u32& r3, u32 a) {
    asm volatile("ldmatrix.sync.aligned.m8n8.x4.trans.shared.b16 {%0,%1,%2,%3}, [%4];"
        : "=r"(r0), "=r"(r1), "=r"(r2), "=r"(r3) : "r"(a));
}
__device__ __forceinline__ void mma16816(float* c, u32 a0, u32 a1, u32 a2, u32 a3, u32 b0, u32 b1) {
    asm volatile("mma.sync.aligned.m16n8k16.row.col.f32.bf16.bf16.f32 "
        "{%0,%1,%2,%3}, {%4,%5,%6,%7}, {%8,%9}, {%0,%1,%2,%3};"
        : "+f"(c[0]), "+f"(c[1]), "+f"(c[2]), "+f"(c[3])
        : "r"(a0), "r"(a1), "r"(a2), "r"(a3), "r"(b0), "r"(b1));
}
// pack 8 fp32 -> 4x u32 of bf16-hi and 4x u32 of bf16-lo
__device__ __forceinline__ void cvt8(const float4& f0, const float4& f1, uint4& hv, uint4& lv) {
    float a[8] = {f0.x, f0.y, f0.z, f0.w, f1.x, f1.y, f1.z, f1.w};
    u32 hw[4], lw[4];
    #pragma unroll
    for (int p = 0; p < 4; p++) {
        bf16 h0 = __float2bfloat16(a[2*p]),   h1 = __float2bfloat16(a[2*p+1]);
        bf16 l0 = __float2bfloat16(a[2*p]   - __bfloat162float(h0));
        bf16 l1 = __float2bfloat16(a[2*p+1] - __bfloat162float(h1));
        __nv_bfloat162 hp = __halves2bfloat162(h0, h1), lp = __halves2bfloat162(l0, l1);
        hw[p] = *(u32*)&hp; lw[p] = *(u32*)&lp;
    }
    hv = make_uint4(hw[0], hw[1], hw[2], hw[3]);
    lv = make_uint4(lw[0], lw[1], lw[2], lw[3]);
}

// ---------------- mma.sync GEMM core ----------------
// 128x128 CTA tile, 8 warps (2x4 -> 64x32 warp tiles), BK=64 bf16.
// A: bf16 hi/lo activations, cp.async double-buffered, SW128-style swizzle.
// B: *** fp32 ROW-MAJOR weights read directly ***: LDG overlapped with compute,
//    converted to bf16 hi/lo in registers, STS into the same swizzled 64x256B
//    layout consumed by ldmatrix.trans. No weight preprocessing kernels at all.
// 3-pass split-bf16: AhBh + AhBl + AlBh, fp32 accum.
// SMEM: [Ah, Al, Bh, Bl] x 16KB x 2 stages = 128KB dynamic.
template<bool GATHER>
__device__ __forceinline__ void mma_core(
    const bf16* __restrict__ Ah, const bf16* __restrict__ Al, int ldA, const int* srow,
    const float* __restrict__ Bf, int ldB,   // fp32 weights, pre-offset to colBase
    int K, char* sm, float (&acc)[4][4][4])
{
    const int TSZ = 16384, STG = 4 * TSZ;
    int tid = threadIdx.x, wid = tid >> 5, lane = tid & 31;
    u32 smb = sm2u(sm);
    auto loadA = [&](int c) {
        u32 sb = smb + (c & 1) * STG;
        int k0 = c * 64;
        #pragma unroll
        for (int it = 0; it < 4; it++) {
            int idx = tid + it * 256;
            int ar = idx >> 3, as = idx & 7;
            u32 soA = (u32)(ar * 128 + ((as ^ (ar & 7)) << 4));
            int arow = GATHER ? srow[ar] : ar;
            size_t ao = ((size_t)arow * ldA + k0 + as * 8) * 2;
            cpa16(sb + soA,       (const char*)Ah + ao);
            cpa16(sb + TSZ + soA, (const char*)Al + ao);
        }
        asm volatile("cp.async.commit_group;" ::: "memory");
    };
    auto ldgB = [&](int c, float4 (&br)[4][2]) {
        int k0 = c * 64;
        #pragma unroll
        for (int u = 0; u < 4; u++) {
            int linear = tid + u * 256;          // 0..1023
            int row = linear >> 4, bs = linear & 15;
            const float* src = Bf + (size_t)(k0 + row) * ldB + bs * 8;
            br[u][0] = *(const float4*)src;
            br[u][1] = *(const float4*)(src + 4);
        }
    };
    auto stsB = [&](int c, float4 (&br)[4][2]) {
        char* sb = sm + (c & 1) * STG;
        #pragma unroll
        for (int u = 0; u < 4; u++) {
            int linear = tid + u * 256;
            int row = linear >> 4, bs = linear & 15;
            u32 so = (u32)(row * 256 + ((bs ^ (row & 7)) << 4));
            uint4 hv, lv;
            cvt8(br[u][0], br[u][1], hv, lv);
            *(uint4*)(sb + 2*TSZ + so) = hv;
            *(uint4*)(sb + 3*TSZ + so) = lv;
        }
    };
    int sub = lane >> 3, l7 = lane & 7, segb = sub >> 1;
    int rA = (wid >> 2) * 64 + l7 + (sub & 1) * 8;
    int NC = K / 64;
    {
        float4 br0[4][2];
        ldgB(0, br0);
        loadA(0);
        stsB(0, br0);
    }
    for (int c = 0; c < NC; c++) {
        float4 brn[4][2];
        if (c + 1 < NC) {
            ldgB(c + 1, brn);
            loadA(c + 1);
            asm volatile("cp.async.wait_group 1;" ::: "memory");
        } else {
            asm volatile("cp.async.wait_group 0;" ::: "memory");
        }
        __syncthreads();           // A(c) cp.async + B(c) STS visible to all
        u32 sb = smb + (c & 1) * STG;
        #pragma unroll
        for (int k16 = 0; k16 < 4; k16++) {
            u32 ah[4][4], al[4][4], bh[2][4], bl[2][4];
            #pragma unroll
            for (int i = 0; i < 4; i++) {
                u32 ra = sb + (u32)((rA + i * 16) * 128 + (((k16 * 2 + segb) ^ (rA & 7)) << 4));
                ldmx4(ah[i][0], ah[i][1], ah[i][2], ah[i][3], ra);
                ldmx4(al[i][0], al[i][1], al[i][2], al[i][3], ra + TSZ);
            }
            #pragma unroll
            for (int jj = 0; jj < 2; jj++) {
                u32 krow = (u32)(k16 * 16 + (sub & 1) * 8 + l7);
                u32 nseg = (u32)((wid & 3) * 4 + jj * 2 + (sub >> 1));
                u32 rb = sb + krow * 256 + ((nseg ^ (krow & 7)) << 4);
                ldmx4t(bh[jj][0], bh[jj][1], bh[jj][2], bh[jj][3], rb + 2*TSZ);
                ldmx4t(bl[jj][0], bl[jj][1], bl[jj][2], bl[jj][3], rb + 3*TSZ);
            }
            #pragma unroll
            for (int i = 0; i < 4; i++)
                #pragma unroll
                for (int j = 0; j < 4; j++) {
                    int jj = j >> 1, o = (j & 1) * 2;
                    mma16816(acc[i][j], ah[i][0], ah[i][1], ah[i][2], ah[i][3], bh[jj][o], bh[jj][o+1]);
                    mma16816(acc[i][j], ah[i][0], ah[i][1], ah[i][2], ah[i][3], bl[jj][o], bl[jj][o+1]);
                    mma16816(acc[i][j], al[i][0], al[i][1], al[i][2], al[i][3], bh[jj][o], bh[jj][o+1]);
                }
        }
        __syncthreads();           // stage (c+1)%2 free for overwrite
        if (c + 1 < NC) stsB(c + 1, brn);
    }
}

#define SMEMG (4*16384*2)

// ---- GEMM kernels (take raw fp32 weight pointers) ----
__global__ void __launch_bounds__(256, 1) k_qkv_mm(const float* __restrict__ wq,
                                                   const float* __restrict__ wk,
                                                   const float* __restrict__ wv) {
    extern __shared__ char sm[];
    int tid = threadIdx.x, wid = tid >> 5, lane = tid & 31;
    int z = blockIdx.z, rowBase = blockIdx.y * 128, colBase = blockIdx.x * 128;
    const float* W = (z == 0) ? wq : (z == 1) ? wk : wv;
    float acc[4][4][4] = {};
    mma_core<false>(g_xn_hi + (size_t)rowBase * Hh, g_xn_lo + (size_t)rowBase * Hh, Hh, nullptr,
                    W + colBase, Hh, Hh, sm, acc);
    float* C = (z == 0) ? g_q : (z == 1) ? g_k : g_v;
    int wR = wid >> 2, wC = wid & 3, lr = lane >> 2, lc = (lane & 3) * 2;
    #pragma unroll
    for (int i = 0; i < 4; i++)
        #pragma unroll
        for (int j = 0; j < 4; j++)
            #pragma unroll
            for (int p = 0; p < 2; p++) {
                int row = wR * 64 + i * 16 + lr + p * 8;
                int col = wC * 32 + j * 8 + lc;
                *(float2*)(C + (size_t)(rowBase + row) * Hh + colBase + col) =
                    make_float2(acc[i][j][2*p], acc[i][j][2*p+1]);
            }
}

__global__ void __launch_bounds__(256, 1) k_wo_mm(const float* __restrict__ wo,
                                                  const float* __restrict__ x) {
    extern __shared__ char sm[];
    int tid = threadIdx.x, wid = tid >> 5, lane = tid & 31;
    int rowBase = blockIdx.y * 128, colBase = blockIdx.x * 128;
    float acc[4][4][4] = {};
    mma_core<false>(g_ao_hi + (size_t)rowBase * Hh, g_ao_lo + (size_t)rowBase * Hh, Hh, nullptr,
                    wo + colBase, Hh, Hh, sm, acc);
    int wR = wid >> 2, wC = wid & 3, lr = lane >> 2, lc = (lane & 3) * 2;
    #pragma unroll
    for (int i = 0; i < 4; i++)
        #pragma unroll
        for (int j = 0; j < 4; j++)
            #pragma unroll
            for (int p = 0; p < 2; p++) {
                int row = wR * 64 + i * 16 + lr + p * 8;
                int col = wC * 32 + j * 8 + lc;
                size_t ro = (size_t)(rowBase + row) * Hh + colBase + col;
                float2 xv = *(const float2*)(x + ro);
                *(float2*)(g_h + ro) = make_float2(acc[i][j][2*p] + xv.x, acc[i][j][2*p+1] + xv.y);
            }
}

// h1 pass: writes fp32 t1
__global__ void __launch_bounds__(256, 1) k_h1_mm(const float* __restrict__ w1) {
    int e = blockIdx.z, cnt = g_cnt[e], rtile = blockIdx.y * 128;
    if (rtile >= cnt) return;
    extern __shared__ char sm[];
    __shared__ int s_row[128];
    int tid = threadIdx.x, wid = tid >> 5, lane = tid & 31;
    int base = g_off[e], colBase = blockIdx.x * 128;
    if (tid < 128) { int r = rtile + tid; s_row[tid] = g_tok[base + (r < cnt ? r : cnt - 1)]; }
    __syncthreads();
    float acc[4][4][4] = {};
    mma_core<true>(g_hn_hi, g_hn_lo, Hh, s_row,
                   w1 + (size_t)e * Hh * Ii + colBase, Ii, Hh, sm, acc);
    int wR = wid >> 2, wC = wid & 3, lr = lane >> 2, lc = (lane & 3) * 2;
    #pragma unroll
    for (int i = 0; i < 4; i++)
        #pragma unroll
        for (int j = 0; j < 4; j++)
            #pragma unroll
            for (int p = 0; p < 2; p++) {
                int row = wR * 64 + i * 16 + lr + p * 8;
                if (rtile + row < cnt) {
                    int col = wC * 32 + j * 8 + lc;
                    *(float2*)(g_t1 + (size_t)(base + rtile + row) * Ii + colBase + col) =
                        make_float2(acc[i][j][2*p], acc[i][j][2*p+1]);
                }
            }
}

// h3 pass with fused SwiGLU epilogue: act = silu(t1) * h3 -> bf16 hi/lo
__global__ void __launch_bounds__(256, 1) k_h3_mm(const float* __restrict__ w3) {
    int e = blockIdx.z, cnt = g_cnt[e], rtile = blockIdx.y * 128;
    if (rtile >= cnt) return;
    extern __shared__ char sm[];
    __shared__ int s_row[128];
    int tid = threadIdx.x, wid = tid >> 5, lane = tid & 31;
    int base = g_off[e], colBase = blockIdx.x * 128;
    if (tid < 128) { int r = rtile + tid; s_row[tid] = g_tok[base + (r < cnt ? r : cnt - 1)]; }
    __syncthreads();
    float acc[4][4][4] = {};
    mma_core<true>(g_hn_hi, g_hn_lo, Hh, s_row,
                   w3 + (size_t)e * Hh * Ii + colBase, Ii, Hh, sm, acc);
    int wR = wid >> 2, wC = wid & 3, lr = lane >> 2, lc = (lane & 3) * 2;
    #pragma unroll
    for (int i = 0; i < 4; i++)
        #pragma unroll
        for (int j = 0; j < 4; j++)
            #pragma unroll
            for (int p = 0; p < 2; p++) {
                int row = wR * 64 + i * 16 + lr + p * 8;
                if (rtile + row < cnt) {
                    int col = wC * 32 + j * 8 + lc;
                    size_t ro = (size_t)(base + rtile + row) * Ii + colBase + col;
                    float2 h1v = *(const float2*)(g_t1 + ro);
                    float a0 = (h1v.x / (1.f + __expf(-h1v.x))) * acc[i][j][2*p];
                    float a1 = (h1v.y / (1.f + __expf(-h1v.y))) * acc[i][j][2*p+1];
                    bf16 b0 = __float2bfloat16(a0), b1 = __float2bfloat16(a1);
                    *(__nv_bfloat162*)(g_act_hi + ro) = __halves2bfloat162(b0, b1);
                    *(__nv_bfloat162*)(g_act_lo + ro) = __halves2bfloat162(
                        __float2bfloat16(a0 - __bfloat162float(b0)),
                        __float2bfloat16(a1 - __bfloat162float(b1)));
                }
            }
}

__global__ void __launch_bounds__(256, 1) k_moe2_mm(const float* __restrict__ w2) {
    int e = blockIdx.z, cnt = g_cnt[e], rtile = blockIdx.y * 128;
    if (rtile >= cnt) return;
    extern __shared__ char sm[];
    __shared__ int s_row[128];
    int tid = threadIdx.x, wid = tid >> 5, lane = tid & 31;
    int base = g_off[e], colBase = blockIdx.x * 128;
    if (tid < 128) { int r = rtile + tid; s_row[tid] = base + (r < cnt ? r : cnt - 1); }
    __syncthreads();
    float acc[4][4][4] = {};
    mma_core<true>(g_act_hi, g_act_lo, Ii, s_row,
                   w2 + (size_t)e * Ii * Hh + colBase, Hh, Ii, sm, acc);
    int wR = wid >> 2, wC = wid & 3, lr = lane >> 2, lc = (lane & 3) * 2;
    #pragma unroll
    for (int i = 0; i < 4; i++)
        #pragma unroll
        for (int j = 0; j < 4; j++)
            #pragma unroll
            for (int p = 0; p < 2; p++) {
                int row = wR * 64 + i * 16 + lr + p * 8;
                if (rtile + row < cnt) {
                    int col = wC * 32 + j * 8 + lc;
                    *(float2*)(g_y + (size_t)(base + rtile + row) * Hh + colBase + col) =
                        make_float2(acc[i][j][2*p], acc[i][j][2*p+1]);
                }
            }
}

// ---- elementwise / small kernels ----
__global__ void k_zero() { int i = threadIdx.x; if (i < Ee) { g_cnt[i] = 0; g_fill[i] = 0; } }

__global__ void k_rmsnorm(const float* __restrict__ x, const float* __restrict__ w,
                          float* __restrict__ out, bf16* __restrict__ ohi, bf16* __restrict__ olo) {
    int t = blockIdx.x, i = threadIdx.x;
    float4 v = ((const float4*)(x + (size_t)t * Hh))[i];
    __shared__ float red[256];
    red[i] = v.x*v.x + v.y*v.y + v.z*v.z + v.w*v.w;
    __syncthreads();
    for (int s = 128; s > 0; s >>= 1) { if (i < s) red[i] += red[i+s]; __syncthreads(); }
    float rinv = rsqrtf(red[0] * (1.0f / Hh) + 1e-6f);
    float4 wv = ((const float4*)w)[i];
    float4 o = make_float4(v.x*rinv*wv.x, v.y*rinv*wv.y, v.z*rinv*wv.z, v.w*rinv*wv.w);
    ((float4*)(out + (size_t)t * Hh))[i] = o;
    float ov[4] = {o.x, o.y, o.z, o.w};
    bf16 hh[4], ll[4];
    #pragma unroll
    for (int j = 0; j < 4; j++) {
        hh[j] = __float2bfloat16(ov[j]);
        ll[j] = __float2bfloat16(ov[j] - __bfloat162float(hh[j]));
    }
    *(__nv_bfloat162*)(ohi + (size_t)t*Hh + 4*i)     = __halves2bfloat162(hh[0], hh[1]);
    *(__nv_bfloat162*)(ohi + (size_t)t*Hh + 4*i + 2) = __halves2bfloat162(hh[2], hh[3]);
    *(__nv_bfloat162*)(olo + (size_t)t*Hh + 4*i)     = __halves2bfloat162(ll[0], ll[1]);
    *(__nv_bfloat162*)(olo + (size_t)t*Hh + 4*i + 2) = __halves2bfloat162(ll[2], ll[3]);
}

__global__ void k_rope(const float* __restrict__ fc) {
    int idx = blockIdx.x * blockDim.x + threadIdx.x;
    float* X = (blockIdx.y == 0) ? g_q : g_k;
    int j = idx & 31, head = (idx >> 5) & (NHh - 1), t = idx >> 9;
    if (t >= Tt) return;
    int s = t & (Ss - 1);
    float2* p = (float2*)(X + (size_t)t * Hh + head * HDd + 2*j);
    float2 ab = *p;
    float cr = fc[s * HDd + 2*j], ci = fc[s * HDd + 2*j + 1];
    *p = make_float2(ab.x*cr - ab.y*ci, ab.x*ci + ab.y*cr);
}

__device__ __forceinline__ void attn_update(float s, float vx, float vy,
                                            float& m, float& l, float& ax, float& ay) {
    float mn = fmaxf(m, s), sc = __expf(m - mn), p = __expf(s - mn);
    l = l*sc + p; ax = ax*sc + p*vx; ay = ay*sc + p*vy; m = mn;
}

// R13 version: one query per warp, 4-row unroll
__global__ void k_attn() {
    int gw = (blockIdx.x * blockDim.x + threadIdx.x) >> 5, lane = threadIdx.x & 31;
    if (gw >= Bb * NHh * Ss) return;
    int qi = gw & (Ss - 1), bh = gw >> 10, head = bh & (NHh - 1), b = bh >> 4;
    float2 qv = *(const float2*)(g_q + (size_t)(b*Ss + qi) * Hh + head*HDd + 2*lane);
    qv.x *= 0.125f; qv.y *= 0.125f;
    const float* kb = g_k + ((size_t)b*Ss*Hh + head*HDd + 2*lane);
    const float* vb = g_v + ((size_t)b*Ss*Hh + head*HDd + 2*lane);
    float m = -1e30f, l = 0.f, ax = 0.f, ay = 0.f;
    int nk = qi + 1, j = 0;
    for (; j + 4 <= nk; j += 4) {
        float2 k0 = *(const float2*)(kb + (size_t)(j+0)*Hh), k1 = *(const float2*)(kb + (size_t)(j+1)*Hh);
        float2 k2 = *(const float2*)(kb + (size_t)(j+2)*Hh), k3 = *(const float2*)(kb + (size_t)(j+3)*Hh);
        float s0 = qv.x*k0.x + qv.y*k0.y, s1 = qv.x*k1.x + qv.y*k1.y;
        float s2 = qv.x*k2.x + qv.y*k2.y, s3 = qv.x*k3.x + qv.y*k3.y;
        #pragma unroll
        for (int o = 16; o > 0; o >>= 1) {
            s0 += __shfl_xor_sync(0xffffffffu, s0, o); s1 += __shfl_xor_sync(0xffffffffu, s1, o);
            s2 += __shfl_xor_sync(0xffffffffu, s2, o); s3 += __shfl_xor_sync(0xffffffffu, s3, o);
        }
        float2 v0 = *(const float2*)(vb + (size_t)(j+0)*Hh), v1 = *(const float2*)(vb + (size_t)(j+1)*Hh);
        float2 v2 = *(const float2*)(vb + (size_t)(j+2)*Hh), v3 = *(const float2*)(vb + (size_t)(j+3)*Hh);
        attn_update(s0, v0.x, v0.y, m, l, ax, ay); attn_update(s1, v1.x, v1.y, m, l, ax, ay);
        attn_update(s2, v2.x, v2.y, m, l, ax, ay); attn_update(s3, v3.x, v3.y, m, l, ax, ay);
    }
    for (; j < nk; j++) {
        float2 kv = *(const float2*)(kb + (size_t)j*Hh);
        float s = qv.x*kv.x + qv.y*kv.y;
        #pragma unroll
        for (int o = 16; o > 0; o >>= 1) s += __shfl_xor_sync(0xffffffffu, s, o);
        float2 vv = *(const float2*)(vb + (size_t)j*Hh);
        attn_update(s, vv.x, vv.y, m, l, ax, ay);
    }
    float inv = 1.f / l;
    float ox = ax*inv, oy = ay*inv;
    size_t oo = (size_t)(b*Ss + qi) * Hh + head*HDd + 2*lane;
    bf16 hx = __float2bfloat16(ox), hy = __float2bfloat16(oy);
    *(__nv_bfloat162*)(g_ao_hi + oo) = __halves2bfloat162(hx, hy);
    *(__nv_bfloat162*)(g_ao_lo + oo) = __halves2bfloat162(
        __float2bfloat16(ox - __bfloat162float(hx)), __float2bfloat16(oy - __bfloat162float(hy)));
}

__global__ void k_router(const float* __restrict__ rw) {
    int t = (blockIdx.x * blockDim.x + threadIdx.x) >> 5, lane = threadIdx.x & 31;
    if (t >= Tt) return;
    const float* xr = g_hn + (size_t)t * Hh;
    float acc[Ee] = {};
    for (int hh = lane; hh < Hh; hh += 32) {
        float xv = xr[hh];
        #pragma unroll
        for (int e = 0; e < Ee; e++) acc[e] += xv * rw[hh * Ee + e];
    }
    #pragma unroll
    for (int e = 0; e < Ee; e++)
        #pragma unroll
        for (int o = 16; o > 0; o >>= 1) acc[e] += __shfl_xor_sync(0xffffffffu, acc[e], o);
    if (lane == 0) {
        float mx = acc[0];
        #pragma unroll
        for (int e = 1; e < Ee; e++) mx = fmaxf(mx, acc[e]);
        float p[Ee], s = 0.f;
        #pragma unroll
        for (int e = 0; e < Ee; e++) { p[e] = __expf(acc[e] - mx); s += p[e]; }
        float invs = 1.f / s;
        #pragma unroll
        for (int e = 0; e < Ee; e++) p[e] *= invs;
        int i1 = 0; float v1 = p[0];
        #pragma unroll
        for (int e = 1; e < Ee; e++) if (p[e] > v1) { v1 = p[e]; i1 = e; }
        int i2 = -1; float v2 = -1.f;
        #pragma unroll
        for (int e = 0; e < Ee; e++) if (e != i1 && p[e] > v2) { v2 = p[e]; i2 = e; }
        float inv = 1.f / (v1 + v2);
        g_topi[t*2] = i1; g_topi[t*2+1] = i2;
        g_topw[t*2] = v1 * inv; g_topw[t*2+1] = v2 * inv;
        atomicAdd(&g_cnt[i1], 1); atomicAdd(&g_cnt[i2], 1);
    }
}

__global__ void k_scan() {
    if (threadIdx.x == 0) {
        int o = 0;
        for (int e = 0; e < Ee; e++) { g_off[e] = o; o += g_cnt[e]; g_fill[e] = 0; }
    }
}

__global__ void k_fill() {
    int t = blockIdx.x * blockDim.x + threadIdx.x;
    if (t >= Tt) return;
    for (int kk = 0; kk < 2; kk++) {
        int e = g_topi[t*2 + kk];
        int slot = g_off[e] + atomicAdd(&g_fill[e], 1);
        g_tok[slot] = t; g_slot[t*2 + kk] = slot;
    }
}

__global__ void k_combine(float* __restrict__ out) {
    int t = blockIdx.x, i = threadIdx.x;
    int s0 = g_slot[t*2], s1 = g_slot[t*2+1];
    float w0 = g_topw[t*2], w1 = g_topw[t*2+1];
    float4 hv = ((const float4*)g_h)[(size_t)t*256 + i];
    float4 y0 = ((const float4*)g_y)[(size_t)s0*256 + i];
    float4 y1 = ((const float4*)g_y)[(size_t)s1*256 + i];
    ((float4*)out)[(size_t)t*256 + i] = make_float4(
        hv.x + w0*y0.x + w1*y1.x, hv.y + w0*y0.y + w1*y1.y,
        hv.z + w0*y0.z + w1*y1.z, hv.w + w0*y0.w + w1*y1.w);
}

// ---------------- launch ----------------
extern "C" void kernel_launch(void* const* d_in, const int* in_sizes, int n_in,
                              void* d_out, int out_size) {
    const float* x   = (const float*)d_in[0];
    const float* anw = (const float*)d_in[1];
    const float* fnw = (const float*)d_in[2];
    const float* wq  = (const float*)d_in[3];
    const float* wk  = (const float*)d_in[4];
    const float* wv  = (const float*)d_in[5];
    const float* wo  = (const float*)d_in[6];
    const float* rw  = (const float*)d_in[7];
    const float* w1  = (const float*)d_in[8];
    const float* w3  = (const float*)d_in[9];
    const float* w2  = (const float*)d_in[10];
    const float* fc  = (const float*)d_in[11];
    float* out = (float*)d_out;

    static int init = 0;
    if (!init) {
        cudaFuncSetAttribute(k_qkv_mm,  cudaFuncAttributeMaxDynamicSharedMemorySize, SMEMG);
        cudaFuncSetAttribute(k_wo_mm,   cudaFuncAttributeMaxDynamicSharedMemorySize, SMEMG);
        cudaFuncSetAttribute(k_h1_mm,   cudaFuncAttributeMaxDynamicSharedMemorySize, SMEMG);
        cudaFuncSetAttribute(k_h3_mm,   cudaFuncAttributeMaxDynamicSharedMemorySize, SMEMG);
        cudaFuncSetAttribute(k_moe2_mm, cudaFuncAttributeMaxDynamicSharedMemorySize, SMEMG);
        init = 1;
    }

    float *d_xn, *d_h, *d_hn;
    bf16 *d_xnh, *d_xnl, *d_hnh, *d_hnl;
    cudaGetSymbolAddress((void**)&d_xn, g_xn);   cudaGetSymbolAddress((void**)&d_h, g_h);
    cudaGetSymbolAddress((void**)&d_hn, g_hn);
    cudaGetSymbolAddress((void**)&d_xnh, g_xn_hi); cudaGetSymbolAddress((void**)&d_xnl, g_xn_lo);
    cudaGetSymbolAddress((void**)&d_hnh, g_hn_hi); cudaGetSymbolAddress((void**)&d_hnl, g_hn_lo);

    k_zero<<<1, 32>>>();
    k_rmsnorm<<<Tt, 256>>>(x, anw, d_xn, d_xnh, d_xnl);
    k_qkv_mm<<<dim3(Hh/128, Tt/128, 3), 256, SMEMG>>>(wq, wk, wv);
    k_rope<<<dim3((Tt * NHh * 32) / 256, 2), 256>>>(fc);
    k_attn<<<(Bb * NHh * Ss) / 4, 128>>>();
    k_wo_mm<<<dim3(Hh/128, Tt/128), 256, SMEMG>>>(wo, x);
    k_rmsnorm<<<Tt, 256>>>(d_h, fnw, d_hn, d_hnh, d_hnl);
    k_router<<<Tt / 8, 256>>>(rw);
    k_scan<<<1, 32>>>();
    k_fill<<<Tt / 256, 256>>>();
    k_h1_mm<<<dim3(Ii/128, Tt/128, Ee), 256, SMEMG>>>(w1);
    k_h3_mm<<<dim3(Ii/128, Tt/128, Ee), 256, SMEMG>>>(w3);
    k_moe2_mm<<<dim3(Hh/128, Tt/128, Ee), 256, SMEMG>>>(w2);
    k_combine<<<Tt, 256>>>(out);
}

// round 16
// speedup vs baseline: 1.0095x; 1.0095x over previous
#include <cuda_runtime.h>
#include <cuda_bf16.h>
#include <math.h>
#include <stdint.h>

typedef unsigned int u32; typedef unsigned long long u64;
typedef __nv_bfloat16 bf16;

#define Bb   2
#define Ss   1024
#define Tt   2048
#define Hh   1024
#define NHh  16
#define HDd  64
#define Ee   8
#define Ii   2048
#define NSLOT (Tt*2)

// ---- fp32 scratch ----
__device__ float g_xn[Tt*Hh];
__device__ float g_q [Tt*Hh];
__device__ float g_k [Tt*Hh];
__device__ float g_v [Tt*Hh];
__device__ float g_h [Tt*Hh];
__device__ float g_hn[Tt*Hh];
__device__ float g_y [NSLOT*Hh];
__device__ float g_t1[NSLOT*Ii];
__device__ int   g_topi[Tt*2];
__device__ float g_topw[Tt*2];
__device__ int   g_slot[Tt*2];
__device__ int   g_tok [NSLOT];
__device__ int   g_cnt [Ee];
__device__ int   g_off [Ee];
__device__ int   g_fill[Ee];

// ---- bf16 split scratch (weights row-major; no transpose) ----
__device__ __align__(16) bf16 g_xn_hi[Tt*Hh],  g_xn_lo[Tt*Hh];
__device__ __align__(16) bf16 g_hn_hi[Tt*Hh],  g_hn_lo[Tt*Hh];
__device__ __align__(16) bf16 g_ao_hi[Tt*Hh],  g_ao_lo[Tt*Hh];
__device__ __align__(16) bf16 g_act_hi[NSLOT*Ii], g_act_lo[NSLOT*Ii];
__device__ __align__(16) bf16 g_wqkv_hi[3*Hh*Hh], g_wqkv_lo[3*Hh*Hh];   // [z][H][H]
__device__ __align__(16) bf16 g_wo_hi[Hh*Hh],     g_wo_lo[Hh*Hh];       // [H][H]
__device__ __align__(16) bf16 g_w1_hi[Ee*Hh*Ii],  g_w1_lo[Ee*Hh*Ii];    // [e][H][I]
__device__ __align__(16) bf16 g_w3_hi[Ee*Hh*Ii],  g_w3_lo[Ee*Hh*Ii];    // [e][H][I]
__device__ __align__(16) bf16 g_w2_hi[Ee*Ii*Hh],  g_w2_lo[Ee*Ii*Hh];    // [e][I][H]

// ---------------- low-level helpers (plain-sm_103-legal) ----------------
__device__ __forceinline__ u32 sm2u(const void* p) {
    u32 a; asm("{ .reg .u64 t; cvta.to.shared.u64 t, %1; cvt.u32.u64 %0, t; }" : "=r"(a) : "l"(p)); return a;
}
__device__ __forceinline__ void cpa16(u32 dst, const void* src) {
    asm volatile("cp.async.cg.shared.global [%0], [%1], 16;" :: "r"(dst), "l"(src));
}
__device__ __forceinline__ void ldmx4(u32& r0, u32& r1, u32& r2, u32& r3, u32 a) {
    asm volatile("ldmatrix.sync.aligned.m8n8.x4.shared.b16 {%0,%1,%2,%3}, [%4];"
        : "=r"(r0), "=r"(r1), "=r"(r2), "=r"(r3) : "r"(a));
}
__device__ __forceinline__ void ldmx4t(u32& r0, u32& r1, u32& r2, u32& r3, u32 a) {
    asm volatile("ldmatrix.sync.aligned.m8n8.x4.trans.shared.b16 {%0,%1,%2,%3}, [%4];"
        : "=r"(r0), "=r"(r1), "=r"(r2), "=r"(r3) : "r"(a));
}
__device__ __forceinline__ void mma16816(float* c, u32 a0, u32 a1, u32 a2, u32 a3, u32 b0, u32 b1) {
    asm volatile("mma.sync.aligned.m16n8k16.row.col.f32.bf16.bf16.f32 "
        "{%0,%1,%2,%3}, {%4,%5,%6,%7}, {%8,%9}, {%0,%1,%2,%3};"
        : "+f"(c[0]), "+f"(c[1]), "+f"(c[2]), "+f"(c[3])
        : "r"(a0), "r"(a1), "r"(a2), "r"(a3), "r"(b0), "r"(b1));
}

// ---------------- mma.sync GEMM core (identical to R13 winner) ----------------
template<bool GATHER>
__device__ __forceinline__ void mma_core(
    const bf16* __restrict__ Ah, const bf16* __restrict__ Al, int ldA, const int* srow,
    const bf16* __restrict__ Bh, const bf16* __restrict__ Bl, int ldB,
    int K, char* sm, float (&acc)[4][4][4])
{
    const int TSZ = 16384, STG = 4 * TSZ;
    int tid = threadIdx.x, wid = tid >> 5, lane = tid & 31;
    u32 smb = sm2u(sm);
    auto load = [&](int c) {
        u32 sb = smb + (c & 1) * STG;
        int k0 = c * 64;
        #pragma unroll
        for (int it = 0; it < 4; it++) {
            int idx = tid + it * 256;
            int ar = idx >> 3, as = idx & 7;
            u32 soA = (u32)(ar * 128 + ((as ^ (ar & 7)) << 4));
            int arow = GATHER ? srow[ar] : ar;
            size_t ao = ((size_t)arow * ldA + k0 + as * 8) * 2;
            cpa16(sb + soA,       (const char*)Ah + ao);
            cpa16(sb + TSZ + soA, (const char*)Al + ao);
            int br = idx >> 4, bs = idx & 15;
            u32 soB = (u32)(br * 256 + ((bs ^ (br & 7)) << 4));
            size_t bo = ((size_t)(k0 + br) * ldB + bs * 8) * 2;
            cpa16(sb + 2*TSZ + soB, (const char*)Bh + bo);
            cpa16(sb + 3*TSZ + soB, (const char*)Bl + bo);
        }
        asm volatile("cp.async.commit_group;" ::: "memory");
    };
    int sub = lane >> 3, l7 = lane & 7, segb = sub >> 1;
    int rA = (wid >> 2) * 64 + l7 + (sub & 1) * 8;
    int NC = K / 64;
    load(0);
    for (int c = 0; c < NC; c++) {
        if (c + 1 < NC) { load(c + 1); asm volatile("cp.async.wait_group 1;" ::: "memory"); }
        else            {              asm volatile("cp.async.wait_group 0;" ::: "memory"); }
        __syncthreads();
        u32 sb = smb + (c & 1) * STG;
        #pragma unroll
        for (int k16 = 0; k16 < 4; k16++) {
            u32 ah[4][4], al[4][4], bh[2][4], bl[2][4];
            #pragma unroll
            for (int i = 0; i < 4; i++) {
                u32 ra = sb + (u32)((rA + i * 16) * 128 + (((k16 * 2 + segb) ^ (rA & 7)) << 4));
                ldmx4(ah[i][0], ah[i][1], ah[i][2], ah[i][3], ra);
                ldmx4(al[i][0], al[i][1], al[i][2], al[i][3], ra + TSZ);
            }
            #pragma unroll
            for (int jj = 0; jj < 2; jj++) {
                u32 krow = (u32)(k16 * 16 + (sub & 1) * 8 + l7);
                u32 nseg = (u32)((wid & 3) * 4 + jj * 2 + (sub >> 1));
                u32 rb = sb + krow * 256 + ((nseg ^ (krow & 7)) << 4);
                ldmx4t(bh[jj][0], bh[jj][1], bh[jj][2], bh[jj][3], rb + 2*TSZ);
                ldmx4t(bl[jj][0], bl[jj][1], bl[jj][2], bl[jj][3], rb + 3*TSZ);
            }
            #pragma unroll
            for (int i = 0; i < 4; i++)
                #pragma unroll
                for (int j = 0; j < 4; j++) {
                    int jj = j >> 1, o = (j & 1) * 2;
                    mma16816(acc[i][j], ah[i][0], ah[i][1], ah[i][2], ah[i][3], bh[jj][o], bh[jj][o+1]);
                    mma16816(acc[i][j], ah[i][0], ah[i][1], ah[i][2], ah[i][3], bl[jj][o], bl[jj][o+1]);
                    mma16816(acc[i][j], al[i][0], al[i][1], al[i][2], al[i][3], bh[jj][o], bh[jj][o+1]);
                }
        }
        __syncthreads();
    }
}

#define SMEMG (4*16384*2)

// ---- GEMM kernels ----
__global__ void __launch_bounds__(256, 1) k_qkv_mm() {
    extern __shared__ char sm[];
    int tid = threadIdx.x, wid = tid >> 5, lane = tid & 31;
    int z = blockIdx.z, rowBase = blockIdx.y * 128, colBase = blockIdx.x * 128;
    float acc[4][4][4] = {};
    mma_core<false>(g_xn_hi + (size_t)rowBase * Hh, g_xn_lo + (size_t)rowBase * Hh, Hh, nullptr,
                    g_wqkv_hi + (size_t)z * Hh * Hh + colBase,
                    g_wqkv_lo + (size_t)z * Hh * Hh + colBase, Hh, Hh, sm, acc);
    float* C = (z == 0) ? g_q : (z == 1) ? g_k : g_v;
    int wR = wid >> 2, wC = wid & 3, lr = lane >> 2, lc = (lane & 3) * 2;
    #pragma unroll
    for (int i = 0; i < 4; i++)
        #pragma unroll
        for (int j = 0; j < 4; j++)
            #pragma unroll
            for (int p = 0; p < 2; p++) {
                int row = wR * 64 + i * 16 + lr + p * 8;
                int col = wC * 32 + j * 8 + lc;
                *(float2*)(C + (size_t)(rowBase + row) * Hh + colBase + col) =
                    make_float2(acc[i][j][2*p], acc[i][j][2*p+1]);
            }
}

__global__ void __launch_bounds__(256, 1) k_wo_mm(const float* __restrict__ x) {
    extern __shared__ char sm[];
    int tid = threadIdx.x, wid = tid >> 5, lane = tid & 31;
    int rowBase = blockIdx.y * 128, colBase = blockIdx.x * 128;
    float acc[4][4][4] = {};
    mma_core<false>(g_ao_hi + (size_t)rowBase * Hh, g_ao_lo + (size_t)rowBase * Hh, Hh, nullptr,
                    g_wo_hi + colBase, g_wo_lo + colBase, Hh, Hh, sm, acc);
    int wR = wid >> 2, wC = wid & 3, lr = lane >> 2, lc = (lane & 3) * 2;
    #pragma unroll
    for (int i = 0; i < 4; i++)
        #pragma unroll
        for (int j = 0; j < 4; j++)
            #pragma unroll
            for (int p = 0; p < 2; p++) {
                int row = wR * 64 + i * 16 + lr + p * 8;
                int col = wC * 32 + j * 8 + lc;
                size_t ro = (size_t)(rowBase + row) * Hh + colBase + col;
                float2 xv = *(const float2*)(x + ro);
                *(float2*)(g_h + ro) = make_float2(acc[i][j][2*p] + xv.x, acc[i][j][2*p+1] + xv.y);
            }
}

// h1 pass: writes fp32 t1
__global__ void __launch_bounds__(256, 1) k_h1_mm() {
    int e = blockIdx.z, cnt = g_cnt[e], rtile = blockIdx.y * 128;
    if (rtile >= cnt) return;
    extern __shared__ char sm[];
    __shared__ int s_row[128];
    int tid = threadIdx.x, wid = tid >> 5, lane = tid & 31;
    int base = g_off[e], colBase = blockIdx.x * 128;
    if (tid < 128) { int r = rtile + tid; s_row[tid] = g_tok[base + (r < cnt ? r : cnt - 1)]; }
    __syncthreads();
    float acc[4][4][4] = {};
    mma_core<true>(g_hn_hi, g_hn_lo, Hh, s_row,
                   g_w1_hi + (size_t)e * Hh * Ii + colBase,
                   g_w1_lo + (size_t)e * Hh * Ii + colBase, Ii, Hh, sm, acc);
    int wR = wid >> 2, wC = wid & 3, lr = lane >> 2, lc = (lane & 3) * 2;
    #pragma unroll
    for (int i = 0; i < 4; i++)
        #pragma unroll
        for (int j = 0; j < 4; j++)
            #pragma unroll
            for (int p = 0; p < 2; p++) {
                int row = wR * 64 + i * 16 + lr + p * 8;
                if (rtile + row < cnt) {
                    int col = wC * 32 + j * 8 + lc;
                    *(float2*)(g_t1 + (size_t)(base + rtile + row) * Ii + colBase + col) =
                        make_float2(acc[i][j][2*p], acc[i][j][2*p+1]);
                }
            }
}

// h3 pass with fused SwiGLU epilogue: act = silu(t1) * h3 -> bf16 hi/lo
__global__ void __launch_bounds__(256, 1) k_h3_mm() {
    int e = blockIdx.z, cnt = g_cnt[e], rtile = blockIdx.y * 128;
    if (rtile >= cnt) return;
    extern __shared__ char sm[];
    __shared__ int s_row[128];
    int tid = threadIdx.x, wid = tid >> 5, lane = tid & 31;
    int base = g_off[e], colBase = blockIdx.x * 128;
    if (tid < 128) { int r = rtile + tid; s_row[tid] = g_tok[base + (r < cnt ? r : cnt - 1)]; }
    __syncthreads();
    float acc[4][4][4] = {};
    mma_core<true>(g_hn_hi, g_hn_lo, Hh, s_row,
                   g_w3_hi + (size_t)e * Hh * Ii + colBase,
                   g_w3_lo + (size_t)e * Hh * Ii + colBase, Ii, Hh, sm, acc);
    int wR = wid >> 2, wC = wid & 3, lr = lane >> 2, lc = (lane & 3) * 2;
    #pragma unroll
    for (int i = 0; i < 4; i++)
        #pragma unroll
        for (int j = 0; j < 4; j++)
            #pragma unroll
            for (int p = 0; p < 2; p++) {
                int row = wR * 64 + i * 16 + lr + p * 8;
                if (rtile + row < cnt) {
                    int col = wC * 32 + j * 8 + lc;
                    size_t ro = (size_t)(base + rtile + row) * Ii + colBase + col;
                    float2 h1v = *(const float2*)(g_t1 + ro);
                    float a0 = (h1v.x / (1.f + __expf(-h1v.x))) * acc[i][j][2*p];
                    float a1 = (h1v.y / (1.f + __expf(-h1v.y))) * acc[i][j][2*p+1];
                    bf16 b0 = __float2bfloat16(a0), b1 = __float2bfloat16(a1);
                    *(__nv_bfloat162*)(g_act_hi + ro) = __halves2bfloat162(b0, b1);
                    *(__nv_bfloat162*)(g_act_lo + ro) = __halves2bfloat162(
                        __float2bfloat16(a0 - __bfloat162float(b0)),
                        __float2bfloat16(a1 - __bfloat162float(b1)));
                }
            }
}

__global__ void __launch_bounds__(256, 1) k_moe2_mm() {
    int e = blockIdx.z, cnt = g_cnt[e], rtile = blockIdx.y * 128;
    if (rtile >= cnt) return;
    extern __shared__ char sm[];
    __shared__ int s_row[128];
    int tid = threadIdx.x, wid = tid >> 5, lane = tid & 31;
    int base = g_off[e], colBase = blockIdx.x * 128;
    if (tid < 128) { int r = rtile + tid; s_row[tid] = base + (r < cnt ? r : cnt - 1); }
    __syncthreads();
    float acc[4][4][4] = {};
    mma_core<true>(g_act_hi, g_act_lo, Ii, s_row,
                   g_w2_hi + (size_t)e * Ii * Hh + colBase,
                   g_w2_lo + (size_t)e * Ii * Hh + colBase, Hh, Ii, sm, acc);
    int wR = wid >> 2, wC = wid & 3, lr = lane >> 2, lc = (lane & 3) * 2;
    #pragma unroll
    for (int i = 0; i < 4; i++)
        #pragma unroll
        for (int j = 0; j < 4; j++)
            #pragma unroll
            for (int p = 0; p < 2; p++) {
                int row = wR * 64 + i * 16 + lr + p * 8;
                if (rtile + row < cnt) {
                    int col = wC * 32 + j * 8 + lc;
                    *(float2*)(g_y + (size_t)(base + rtile + row) * Hh + colBase + col) =
                        make_float2(acc[i][j][2*p], acc[i][j][2*p+1]);
                }
            }
}

// ---- pure elementwise split: fp32 -> bf16 hi/lo (R13 version) ----
__global__ void k_split(const float* __restrict__ in, bf16* __restrict__ oh,
                        bf16* __restrict__ ol, int n4) {
    int i = blockIdx.x * blockDim.x + threadIdx.x;
    if (i >= n4) return;
    float4 v = ((const float4*)in)[i];
    float a[4] = {v.x, v.y, v.z, v.w};
    bf16 h[4], l[4];
    #pragma unroll
    for (int j = 0; j < 4; j++) {
        h[j] = __float2bfloat16(a[j]);
        l[j] = __float2bfloat16(a[j] - __bfloat162float(h[j]));
    }
    *(__nv_bfloat162*)(oh + 4*(size_t)i)     = __halves2bfloat162(h[0], h[1]);
    *(__nv_bfloat162*)(oh + 4*(size_t)i + 2) = __halves2bfloat162(h[2], h[3]);
    *(__nv_bfloat162*)(ol + 4*(size_t)i)     = __halves2bfloat162(l[0], l[1]);
    *(__nv_bfloat162*)(ol + 4*(size_t)i + 2) = __halves2bfloat162(l[2], l[3]);
}

// ---- elementwise / small kernels ----
__global__ void k_zero() { int i = threadIdx.x; if (i < Ee) { g_cnt[i] = 0; g_fill[i] = 0; } }

__global__ void k_rmsnorm(const float* __restrict__ x, const float* __restrict__ w,
                          float* __restrict__ out, bf16* __restrict__ ohi, bf16* __restrict__ olo) {
    int t = blockIdx.x, i = threadIdx.x;
    float4 v = ((const float4*)(x + (size_t)t * Hh))[i];
    __shared__ float red[256];
    red[i] = v.x*v.x + v.y*v.y + v.z*v.z + v.w*v.w;
    __syncthreads();
    for (int s = 128; s > 0; s >>= 1) { if (i < s) red[i] += red[i+s]; __syncthreads(); }
    float rinv = rsqrtf(red[0] * (1.0f / Hh) + 1e-6f);
    float4 wv = ((const float4*)w)[i];
    float4 o = make_float4(v.x*rinv*wv.x, v.y*rinv*wv.y, v.z*rinv*wv.z, v.w*rinv*wv.w);
    ((float4*)(out + (size_t)t * Hh))[i] = o;
    float ov[4] = {o.x, o.y, o.z, o.w};
    bf16 hh[4], ll[4];
    #pragma unroll
    for (int j = 0; j < 4; j++) {
        hh[j] = __float2bfloat16(ov[j]);
        ll[j] = __float2bfloat16(ov[j] - __bfloat162float(hh[j]));
    }
    *(__nv_bfloat162*)(ohi + (size_t)t*Hh + 4*i)     = __halves2bfloat162(hh[0], hh[1]);
    *(__nv_bfloat162*)(ohi + (size_t)t*Hh + 4*i + 2) = __halves2bfloat162(hh[2], hh[3]);
    *(__nv_bfloat162*)(olo + (size_t)t*Hh + 4*i)     = __halves2bfloat162(ll[0], ll[1]);
    *(__nv_bfloat162*)(olo + (size_t)t*Hh + 4*i + 2) = __halves2bfloat162(ll[2], ll[3]);
}

__global__ void k_rope(const float* __restrict__ fc) {
    int idx = blockIdx.x * blockDim.x + threadIdx.x;
    float* X = (blockIdx.y == 0) ? g_q : g_k;
    int j = idx & 31, head = (idx >> 5) & (NHh - 1), t = idx >> 9;
    if (t >= Tt) return;
    int s = t & (Ss - 1);
    float2* p = (float2*)(X + (size_t)t * Hh + head * HDd + 2*j);
    float2 ab = *p;
    float cr = fc[s * HDd + 2*j], ci = fc[s * HDd + 2*j + 1];
    *p = make_float2(ab.x*cr - ab.y*ci, ab.x*ci + ab.y*cr);
}

__device__ __forceinline__ void attn_update(float s, float vx, float vy,
                                            float& m, float& l, float& ax, float& ay) {
    float mn = fmaxf(m, s), sc = __expf(m - mn), p = __expf(s - mn);
    l = l*sc + p; ax = ax*sc + p*vx; ay = ay*sc + p*vy; m = mn;
}

// R13 version: one query per warp, 4-row unroll
__global__ void k_attn() {
    int gw = (blockIdx.x * blockDim.x + threadIdx.x) >> 5, lane = threadIdx.x & 31;
    if (gw >= Bb * NHh * Ss) return;
    int qi = gw & (Ss - 1), bh = gw >> 10, head = bh & (NHh - 1), b = bh >> 4;
    float2 qv = *(const float2*)(g_q + (size_t)(b*Ss + qi) * Hh + head*HDd + 2*lane);
    qv.x *= 0.125f; qv.y *= 0.125f;
    const float* kb = g_k + ((size_t)b*Ss*Hh + head*HDd + 2*lane);
    const float* vb = g_v + ((size_t)b*Ss*Hh + head*HDd + 2*lane);
    float m = -1e30f, l = 0.f, ax = 0.f, ay = 0.f;
    int nk = qi + 1, j = 0;
    for (; j + 4 <= nk; j += 4) {
        float2 k0 = *(const float2*)(kb + (size_t)(j+0)*Hh), k1 = *(const float2*)(kb + (size_t)(j+1)*Hh);
        float2 k2 = *(const float2*)(kb + (size_t)(j+2)*Hh), k3 = *(const float2*)(kb + (size_t)(j+3)*Hh);
        float s0 = qv.x*k0.x + qv.y*k0.y, s1 = qv.x*k1.x + qv.y*k1.y;
        float s2 = qv.x*k2.x + qv.y*k2.y, s3 = qv.x*k3.x + qv.y*k3.y;
        #pragma unroll
        for (int o = 16; o > 0; o >>= 1) {
            s0 += __shfl_xor_sync(0xffffffffu, s0, o); s1 += __shfl_xor_sync(0xffffffffu, s1, o);
            s2 += __shfl_xor_sync(0xffffffffu, s2, o); s3 += __shfl_xor_sync(0xffffffffu, s3, o);
        }
        float2 v0 = *(const float2*)(vb + (size_t)(j+0)*Hh), v1 = *(const float2*)(vb + (size_t)(j+1)*Hh);
        float2 v2 = *(const float2*)(vb + (size_t)(j+2)*Hh), v3 = *(const float2*)(vb + (size_t)(j+3)*Hh);
        attn_update(s0, v0.x, v0.y, m, l, ax, ay); attn_update(s1, v1.x, v1.y, m, l, ax, ay);
        attn_update(s2, v2.x, v2.y, m, l, ax, ay); attn_update(s3, v3.x, v3.y, m, l, ax, ay);
    }
    for (; j < nk; j++) {
        float2 kv = *(const float2*)(kb + (size_t)j*Hh);
        float s = qv.x*kv.x + qv.y*kv.y;
        #pragma unroll
        for (int o = 16; o > 0; o >>= 1) s += __shfl_xor_sync(0xffffffffu, s, o);
        float2 vv = *(const float2*)(vb + (size_t)j*Hh);
        attn_update(s, vv.x, vv.y, m, l, ax, ay);
    }
    float inv = 1.f / l;
    float ox = ax*inv, oy = ay*inv;
    size_t oo = (size_t)(b*Ss + qi) * Hh + head*HDd + 2*lane;
    bf16 hx = __float2bfloat16(ox), hy = __float2bfloat16(oy);
    *(__nv_bfloat162*)(g_ao_hi + oo) = __halves2bfloat162(hx, hy);
    *(__nv_bfloat162*)(g_ao_lo + oo) = __halves2bfloat162(
        __float2bfloat16(ox - __bfloat162float(hx)), __float2bfloat16(oy - __bfloat162float(hy)));
}

__global__ void k_router(const float* __restrict__ rw) {
    int t = (blockIdx.x * blockDim.x + threadIdx.x) >> 5, lane = threadIdx.x & 31;
    if (t >= Tt) return;
    const float* xr = g_hn + (size_t)t * Hh;
    float acc[Ee] = {};
    for (int hh = lane; hh < Hh; hh += 32) {
        float xv = xr[hh];
        #pragma unroll
        for (int e = 0; e < Ee; e++) acc[e] += xv * rw[hh * Ee + e];
    }
    #pragma unroll
    for (int e = 0; e < Ee; e++)
        #pragma unroll
        for (int o = 16; o > 0; o >>= 1) acc[e] += __shfl_xor_sync(0xffffffffu, acc[e], o);
    if (lane == 0) {
        float mx = acc[0];
        #pragma unroll
        for (int e = 1; e < Ee; e++) mx = fmaxf(mx, acc[e]);
        float p[Ee], s = 0.f;
        #pragma unroll
        for (int e = 0; e < Ee; e++) { p[e] = __expf(acc[e] - mx); s += p[e]; }
        float invs = 1.f / s;
        #pragma unroll
        for (int e = 0; e < Ee; e++) p[e] *= invs;
        int i1 = 0; float v1 = p[0];
        #pragma unroll
        for (int e = 1; e < Ee; e++) if (p[e] > v1) { v1 = p[e]; i1 = e; }
        int i2 = -1; float v2 = -1.f;
        #pragma unroll
        for (int e = 0; e < Ee; e++) if (e != i1 && p[e] > v2) { v2 = p[e]; i2 = e; }
        float inv = 1.f / (v1 + v2);
        g_topi[t*2] = i1; g_topi[t*2+1] = i2;
        g_topw[t*2] = v1 * inv; g_topw[t*2+1] = v2 * inv;
        atomicAdd(&g_cnt[i1], 1); atomicAdd(&g_cnt[i2], 1);
    }
}

__global__ void k_scan() {
    if (threadIdx.x == 0) {
        int o = 0;
        for (int e = 0; e < Ee; e++) { g_off[e] = o; o += g_cnt[e]; g_fill[e] = 0; }
    }
}

__global__ void k_fill() {
    int t = blockIdx.x * blockDim.x + threadIdx.x;
    if (t >= Tt) return;
    for (int kk = 0; kk < 2; kk++) {
        int e = g_topi[t*2 + kk];
        int slot = g_off[e] + atomicAdd(&g_fill[e], 1);
        g_tok[slot] = t; g_slot[t*2 + kk] = slot;
    }
}

__global__ void k_combine(float* __restrict__ out) {
    int t = blockIdx.x, i = threadIdx.x;
    int s0 = g_slot[t*2], s1 = g_slot[t*2+1];
    float w0 = g_topw[t*2], w1 = g_topw[t*2+1];
    float4 hv = ((const float4*)g_h)[(size_t)t*256 + i];
    float4 y0 = ((const float4*)g_y)[(size_t)s0*256 + i];
    float4 y1 = ((const float4*)g_y)[(size_t)s1*256 + i];
    ((float4*)out)[(size_t)t*256 + i] = make_float4(
        hv.x + w0*y0.x + w1*y1.x, hv.y + w0*y0.y + w1*y1.y,
        hv.z + w0*y0.z + w1*y1.z, hv.w + w0*y0.w + w1*y1.w);
}

// ---------------- launch ----------------
extern "C" void kernel_launch(void* const* d_in, const int* in_sizes, int n_in,
                              void* d_out, int out_size) {
    const float* x   = (const float*)d_in[0];
    const float* anw = (const float*)d_in[1];
    const float* fnw = (const float*)d_in[2];
    const float* wq  = (const float*)d_in[3];
    const float* wk  = (const float*)d_in[4];
    const float* wv  = (const float*)d_in[5];
    const float* wo  = (const float*)d_in[6];
    const float* rw  = (const float*)d_in[7];
    const float* w1  = (const float*)d_in[8];
    const float* w3  = (const float*)d_in[9];
    const float* w2  = (const float*)d_in[10];
    const float* fc  = (const float*)d_in[11];
    float* out = (float*)d_out;

    static int init = 0;
    if (!init) {
        cudaFuncSetAttribute(k_qkv_mm,  cudaFuncAttributeMaxDynamicSharedMemorySize, SMEMG);
        cudaFuncSetAttribute(k_wo_mm,   cudaFuncAttributeMaxDynamicSharedMemorySize, SMEMG);
        cudaFuncSetAttribute(k_h1_mm,   cudaFuncAttributeMaxDynamicSharedMemorySize, SMEMG);
        cudaFuncSetAttribute(k_h3_mm,   cudaFuncAttributeMaxDynamicSharedMemorySize, SMEMG);
        cudaFuncSetAttribute(k_moe2_mm, cudaFuncAttributeMaxDynamicSharedMemorySize, SMEMG);
        init = 1;
    }

    float *d_xn, *d_h, *d_hn;
    bf16 *d_xnh, *d_xnl, *d_hnh, *d_hnl;
    bf16 *d_qkvh, *d_qkvl, *d_woh, *d_wol, *d_w1h, *d_w1l, *d_w3h, *d_w3l, *d_w2h, *d_w2l;
    cudaGetSymbolAddress((void**)&d_xn, g_xn);   cudaGetSymbolAddress((void**)&d_h, g_h);
    cudaGetSymbolAddress((void**)&d_hn, g_hn);
    cudaGetSymbolAddress((void**)&d_xnh, g_xn_hi); cudaGetSymbolAddress((void**)&d_xnl, g_xn_lo);
    cudaGetSymbolAddress((void**)&d_hnh, g_hn_hi); cudaGetSymbolAddress((void**)&d_hnl, g_hn_lo);
    cudaGetSymbolAddress((void**)&d_qkvh, g_wqkv_hi); cudaGetSymbolAddress((void**)&d_qkvl, g_wqkv_lo);
    cudaGetSymbolAddress((void**)&d_woh, g_wo_hi);    cudaGetSymbolAddress((void**)&d_wol, g_wo_lo);
    cudaGetSymbolAddress((void**)&d_w1h, g_w1_hi);    cudaGetSymbolAddress((void**)&d_w1l, g_w1_lo);
    cudaGetSymbolAddress((void**)&d_w3h, g_w3_hi);    cudaGetSymbolAddress((void**)&d_w3l, g_w3_lo);
    cudaGetSymbolAddress((void**)&d_w2h, g_w2_hi);    cudaGetSymbolAddress((void**)&d_w2l, g_w2_lo);

    k_zero<<<1, 32>>>();
    k_split<<<(Hh*Hh/4)/256, 256>>>(wq, d_qkvh,           d_qkvl,           Hh*Hh/4);
    k_split<<<(Hh*Hh/4)/256, 256>>>(wk, d_qkvh + Hh*Hh,   d_qkvl + Hh*Hh,   Hh*Hh/4);
    k_split<<<(Hh*Hh/4)/256, 256>>>(wv, d_qkvh + 2*Hh*Hh, d_qkvl + 2*Hh*Hh, Hh*Hh/4);
    k_split<<<(Hh*Hh/4)/256, 256>>>(wo, d_woh, d_wol, Hh*Hh/4);
    k_split<<<(Ee*Hh*Ii/4)/256, 256>>>(w1, d_w1h, d_w1l, Ee*Hh*Ii/4);
    k_split<<<(Ee*Hh*Ii/4)/256, 256>>>(w3, d_w3h, d_w3l, Ee*Hh*Ii/4);
    k_split<<<(Ee*Ii*Hh/4)/256, 256>>>(w2, d_w2h, d_w2l, Ee*Ii*Hh/4);

    k_rmsnorm<<<Tt, 256>>>(x, anw, d_xn, d_xnh, d_xnl);
    k_qkv_mm<<<dim3(Hh/128, Tt/128, 3), 256, SMEMG>>>();
    k_rope<<<dim3((Tt * NHh * 32) / 256, 2), 256>>>(fc);
    k_attn<<<(Bb * NHh * Ss) / 4, 128>>>();
    k_wo_mm<<<dim3(Hh/128, Tt/128), 256, SMEMG>>>(x);
    k_rmsnorm<<<Tt, 256>>>(d_h, fnw, d_hn, d_hnh, d_hnl);
    k_router<<<Tt / 8, 256>>>(rw);
    k_scan<<<1, 32>>>();
    k_fill<<<Tt / 256, 256>>>();
    k_h1_mm<<<dim3(Ii/128, Tt/128, Ee), 256, SMEMG>>>();
    k_h3_mm<<<dim3(Ii/128, Tt/128, Ee), 256, SMEMG>>>();
    k_moe2_mm<<<dim3(Hh/128, Tt/128, Ee), 256, SMEMG>>>();
    k_combine<<<Tt, 256>>>(out);
}

// round 17
// speedup vs baseline: 1.0430x; 1.0332x over previous
#include <cuda_runtime.h>
#include <cuda_bf16.h>
#include <math.h>
#include <stdint.h>

typedef unsigned int u32; typedef unsigned long long u64;
typedef __nv_bfloat16 bf16;

#define Bb   2
#define Ss   1024
#define Tt   2048
#define Hh   1024
#define NHh  16
#define HDd  64
#define Ee   8
#define Ii   2048
#define NSLOT (Tt*2)

// ---- fp32 scratch ----
__device__ float g_xn[Tt*Hh];
__device__ float g_q [Tt*Hh];
__device__ float g_k [Tt*Hh];
__device__ float g_v [Tt*Hh];
__device__ float g_h [Tt*Hh];
__device__ float g_hn[Tt*Hh];
__device__ float g_y [NSLOT*Hh];
__device__ float g_t1[NSLOT*Ii];
__device__ float g_t3[NSLOT*Ii];
__device__ int   g_topi[Tt*2];
__device__ float g_topw[Tt*2];
__device__ int   g_slot[Tt*2];
__device__ int   g_tok [NSLOT];
__device__ int   g_cnt [Ee];
__device__ int   g_off [Ee];
__device__ int   g_fill[Ee];

// ---- bf16 split scratch (weights row-major; no transpose) ----
__device__ __align__(16) bf16 g_xn_hi[Tt*Hh],  g_xn_lo[Tt*Hh];
__device__ __align__(16) bf16 g_hn_hi[Tt*Hh],  g_hn_lo[Tt*Hh];
__device__ __align__(16) bf16 g_ao_hi[Tt*Hh],  g_ao_lo[Tt*Hh];
__device__ __align__(16) bf16 g_act_hi[NSLOT*Ii], g_act_lo[NSLOT*Ii];
__device__ __align__(16) bf16 g_wqkv_hi[3*Hh*Hh], g_wqkv_lo[3*Hh*Hh];   // [z][H][H]
__device__ __align__(16) bf16 g_wo_hi[Hh*Hh],     g_wo_lo[Hh*Hh];       // [H][H]
__device__ __align__(16) bf16 g_w1_hi[Ee*Hh*Ii],  g_w1_lo[Ee*Hh*Ii];    // [e][H][I]
__device__ __align__(16) bf16 g_w3_hi[Ee*Hh*Ii],  g_w3_lo[Ee*Hh*Ii];    // [e][H][I]
__device__ __align__(16) bf16 g_w2_hi[Ee*Ii*Hh],  g_w2_lo[Ee*Ii*Hh];    // [e][I][H]

// ---------------- low-level helpers (plain-sm_103-legal) ----------------
__device__ __forceinline__ u32 sm2u(const void* p) {
    u32 a; asm("{ .reg .u64 t; cvta.to.shared.u64 t, %1; cvt.u32.u64 %0, t; }" : "=r"(a) : "l"(p)); return a;
}
__device__ __forceinline__ void cpa16(u32 dst, const void* src) {
    asm volatile("cp.async.cg.shared.global [%0], [%1], 16;" :: "r"(dst), "l"(src));
}
__device__ __forceinline__ void ldmx4(u32& r0, u32& r1, u32& r2, u32& r3, u32 a) {
    asm volatile("ldmatrix.sync.aligned.m8n8.x4.shared.b16 {%0,%1,%2,%3}, [%4];"
        : "=r"(r0), "=r"(r1), "=r"(r2), "=r"(r3) : "r"(a));
}
__device__ __forceinline__ void ldmx4t(u32& r0, u32& r1, u32& r2, u32& r3, u32 a) {
    asm volatile("ldmatrix.sync.aligned.m8n8.x4.trans.shared.b16 {%0,%1,%2,%3}, [%4];"
        : "=r"(r0), "=r"(r1), "=r"(r2), "=r"(r3) : "r"(a));
}
__device__ __forceinline__ void mma16816(float* c, u32 a0, u32 a1, u32 a2, u32 a3, u32 b0, u32 b1) {
    asm volatile("mma.sync.aligned.m16n8k16.row.col.f32.bf16.bf16.f32 "
        "{%0,%1,%2,%3}, {%4,%5,%6,%7}, {%8,%9}, {%0,%1,%2,%3};"
        : "+f"(c[0]), "+f"(c[1]), "+f"(c[2]), "+f"(c[3])
        : "r"(a0), "r"(a1), "r"(a2), "r"(a3), "r"(b0), "r"(b1));
}

// ---------------- mma.sync GEMM core, templated CTA width ----------------
// CTA tile 128 x BN (BN = 128 or 256), 8 warps (2x4 -> warp tile 64 x BN/4), BK=64.
// A: bf16 hi/lo K-major, SW-swizzled 128x128B tiles, normal ldmatrix.
// B: bf16 hi/lo ROW-MAJOR [k][n], 64-row x (2*BN)B tiles, seg^(k&7) swizzle,
//    ldmatrix.trans. 3-pass split-bf16: AhBh + AhBl + AlBh, fp32 accum.
template<int BN, bool GATHER>
__device__ __forceinline__ void mma_core(
    const bf16* __restrict__ Ah, const bf16* __restrict__ Al, int ldA, const int* srow,
    const bf16* __restrict__ Bh, const bf16* __restrict__ Bl, int ldB,
    int K, char* sm, float (&acc)[4][8][4])
{
    constexpr int TSZ = 16384;
    constexpr int BTS = 64 * BN * 2;          // B tile bytes per hi/lo
    constexpr int STG = 2 * TSZ + 2 * BTS;    // one stage
    constexpr int JJm = BN / 64;              // 16-col ldmatrix.trans groups per warp
    constexpr int NJ  = BN / 32;              // 8-col j groups per warp
    int tid = threadIdx.x, wid = tid >> 5, lane = tid & 31;
    u32 smb = sm2u(sm);
    auto load = [&](int c) {
        u32 sb = smb + (c & 1) * STG;
        int k0 = c * 64;
        #pragma unroll
        for (int it = 0; it < 4; it++) {           // A: 1024 segs
            int idx = tid + it * 256;
            int ar = idx >> 3, as = idx & 7;
            u32 soA = (u32)(ar * 128 + ((as ^ (ar & 7)) << 4));
            int arow = GATHER ? srow[ar] : ar;
            size_t ao = ((size_t)arow * ldA + k0 + as * 8) * 2;
            cpa16(sb + soA,       (const char*)Ah + ao);
            cpa16(sb + TSZ + soA, (const char*)Al + ao);
        }
        #pragma unroll
        for (int it = 0; it < BN / 32; it++) {     // B: 64*(BN/8) segs
            int idx = tid + it * 256;
            int br = idx / (BN / 8), bs = idx & (BN / 8 - 1);
            u32 soB = (u32)(br * (2 * BN) + ((bs ^ (br & 7)) << 4));
            size_t bo = ((size_t)(k0 + br) * ldB + bs * 8) * 2;
            cpa16(sb + 2*TSZ + soB,       (const char*)Bh + bo);
            cpa16(sb + 2*TSZ + BTS + soB, (const char*)Bl + bo);
        }
        asm volatile("cp.async.commit_group;" ::: "memory");
    };
    int sub = lane >> 3, l7 = lane & 7, segb = sub >> 1;
    int rA = (wid >> 2) * 64 + l7 + (sub & 1) * 8;
    int NC = K / 64;
    load(0);
    for (int c = 0; c < NC; c++) {
        if (c + 1 < NC) { load(c + 1); asm volatile("cp.async.wait_group 1;" ::: "memory"); }
        else            {              asm volatile("cp.async.wait_group 0;" ::: "memory"); }
        __syncthreads();
        u32 sb = smb + (c & 1) * STG;
        #pragma unroll
        for (int k16 = 0; k16 < 4; k16++) {
            u32 ah[4][4], al[4][4], bh[JJm][4], bl[JJm][4];
            #pragma unroll
            for (int i = 0; i < 4; i++) {
                u32 ra = sb + (u32)((rA + i * 16) * 128 + (((k16 * 2 + segb) ^ (rA & 7)) << 4));
                ldmx4(ah[i][0], ah[i][1], ah[i][2], ah[i][3], ra);
                ldmx4(al[i][0], al[i][1], al[i][2], al[i][3], ra + TSZ);
            }
            u32 krow = (u32)(k16 * 16 + (sub & 1) * 8 + l7);
            #pragma unroll
            for (int jj = 0; jj < JJm; jj++) {
                u32 nseg = (u32)((wid & 3) * (2 * JJm) + jj * 2 + (sub >> 1));
                u32 rb = sb + krow * (2 * BN) + ((nseg ^ (krow & 7)) << 4);
                ldmx4t(bh[jj][0], bh[jj][1], bh[jj][2], bh[jj][3], rb + 2*TSZ);
                ldmx4t(bl[jj][0], bl[jj][1], bl[jj][2], bl[jj][3], rb + 2*TSZ + BTS);
            }
            #pragma unroll
            for (int i = 0; i < 4; i++)
                #pragma unroll
                for (int j = 0; j < NJ; j++) {
                    int jj = j >> 1, o = (j & 1) * 2;
                    mma16816(acc[i][j], ah[i][0], ah[i][1], ah[i][2], ah[i][3], bh[jj][o], bh[jj][o+1]);
                    mma16816(acc[i][j], ah[i][0], ah[i][1], ah[i][2], ah[i][3], bl[jj][o], bl[jj][o+1]);
                    mma16816(acc[i][j], al[i][0], al[i][1], al[i][2], al[i][3], bh[jj][o], bh[jj][o+1]);
                }
        }
        __syncthreads();
    }
}

#define SMEM128 (2*(2*16384 + 2*16384))
#define SMEM256 (2*(2*16384 + 2*32768))

// ---- GEMM kernels ----
__global__ void __launch_bounds__(256, 1) k_qkv_mm() {
    extern __shared__ char sm[];
    int tid = threadIdx.x, wid = tid >> 5, lane = tid & 31;
    int z = blockIdx.z, rowBase = blockIdx.y * 128, colBase = blockIdx.x * 256;
    float acc[4][8][4] = {};
    mma_core<256, false>(g_xn_hi + (size_t)rowBase * Hh, g_xn_lo + (size_t)rowBase * Hh, Hh, nullptr,
                         g_wqkv_hi + (size_t)z * Hh * Hh + colBase,
                         g_wqkv_lo + (size_t)z * Hh * Hh + colBase, Hh, Hh, sm, acc);
    float* C = (z == 0) ? g_q : (z == 1) ? g_k : g_v;
    int wR = wid >> 2, wC = wid & 3, lr = lane >> 2, lc = (lane & 3) * 2;
    #pragma unroll
    for (int i = 0; i < 4; i++)
        #pragma unroll
        for (int j = 0; j < 8; j++)
            #pragma unroll
            for (int p = 0; p < 2; p++) {
                int row = wR * 64 + i * 16 + lr + p * 8;
                int col = wC * 64 + j * 8 + lc;
                *(float2*)(C + (size_t)(rowBase + row) * Hh + colBase + col) =
                    make_float2(acc[i][j][2*p], acc[i][j][2*p+1]);
            }
}

__global__ void __launch_bounds__(256, 1) k_wo_mm(const float* __restrict__ x) {
    extern __shared__ char sm[];
    int tid = threadIdx.x, wid = tid >> 5, lane = tid & 31;
    int rowBase = blockIdx.y * 128, colBase = blockIdx.x * 128;
    float acc[4][8][4] = {};
    mma_core<128, false>(g_ao_hi + (size_t)rowBase * Hh, g_ao_lo + (size_t)rowBase * Hh, Hh, nullptr,
                         g_wo_hi + colBase, g_wo_lo + colBase, Hh, Hh, sm, acc);
    int wR = wid >> 2, wC = wid & 3, lr = lane >> 2, lc = (lane & 3) * 2;
    #pragma unroll
    for (int i = 0; i < 4; i++)
        #pragma unroll
        for (int j = 0; j < 4; j++)
            #pragma unroll
            for (int p = 0; p < 2; p++) {
                int row = wR * 64 + i * 16 + lr + p * 8;
                int col = wC * 32 + j * 8 + lc;
                size_t ro = (size_t)(rowBase + row) * Hh + colBase + col;
                float2 xv = *(const float2*)(x + ro);
                *(float2*)(g_h + ro) = make_float2(acc[i][j][2*p] + xv.x, acc[i][j][2*p+1] + xv.y);
            }
}

__global__ void __launch_bounds__(256, 1) k_h13_mm(const bf16* __restrict__ Wh,
                                                  const bf16* __restrict__ Wl,
                                                  float* __restrict__ out) {
    int e = blockIdx.z, cnt = g_cnt[e], rtile = blockIdx.y * 128;
    if (rtile >= cnt) return;
    extern __shared__ char sm[];
    __shared__ int s_row[128];
    int tid = threadIdx.x, wid = tid >> 5, lane = tid & 31;
    int base = g_off[e], colBase = blockIdx.x * 256;
    if (tid < 128) { int r = rtile + tid; s_row[tid] = g_tok[base + (r < cnt ? r : cnt - 1)]; }
    __syncthreads();
    float acc[4][8][4] = {};
    mma_core<256, true>(g_hn_hi, g_hn_lo, Hh, s_row,
                        Wh + (size_t)e * Hh * Ii + colBase, Wl + (size_t)e * Hh * Ii + colBase, Ii,
                        Hh, sm, acc);
    int wR = wid >> 2, wC = wid & 3, lr = lane >> 2, lc = (lane & 3) * 2;
    #pragma unroll
    for (int i = 0; i < 4; i++)
        #pragma unroll
        for (int j = 0; j < 8; j++)
            #pragma unroll
            for (int p = 0; p < 2; p++) {
                int row = wR * 64 + i * 16 + lr + p * 8;
                if (rtile + row < cnt) {
                    int col = wC * 64 + j * 8 + lc;
                    *(float2*)(out + (size_t)(base + rtile + row) * Ii + colBase + col) =
                        make_float2(acc[i][j][2*p], acc[i][j][2*p+1]);
                }
            }
}

__global__ void __launch_bounds__(256, 1) k_moe2_mm() {
    int e = blockIdx.z, cnt = g_cnt[e], rtile = blockIdx.y * 128;
    if (rtile >= cnt) return;
    extern __shared__ char sm[];
    __shared__ int s_row[128];
    int tid = threadIdx.x, wid = tid >> 5, lane = tid & 31;
    int base = g_off[e], colBase = blockIdx.x * 256;
    if (tid < 128) { int r = rtile + tid; s_row[tid] = base + (r < cnt ? r : cnt - 1); }
    __syncthreads();
    float acc[4][8][4] = {};
    mma_core<256, true>(g_act_hi, g_act_lo, Ii, s_row,
                        g_w2_hi + (size_t)e * Ii * Hh + colBase,
                        g_w2_lo + (size_t)e * Ii * Hh + colBase, Hh, Ii, sm, acc);
    int wR = wid >> 2, wC = wid & 3, lr = lane >> 2, lc = (lane & 3) * 2;
    #pragma unroll
    for (int i = 0; i < 4; i++)
        #pragma unroll
        for (int j = 0; j < 8; j++)
            #pragma unroll
            for (int p = 0; p < 2; p++) {
                int row = wR * 64 + i * 16 + lr + p * 8;
                if (rtile + row < cnt) {
                    int col = wC * 64 + j * 8 + lc;
                    *(float2*)(g_y + (size_t)(base + rtile + row) * Hh + colBase + col) =
                        make_float2(acc[i][j][2*p], acc[i][j][2*p+1]);
                }
            }
}

// ---- pure elementwise split: fp32 -> bf16 hi/lo ----
__global__ void k_split(const float* __restrict__ in, bf16* __restrict__ oh,
                        bf16* __restrict__ ol, int n4) {
    int i = blockIdx.x * blockDim.x + threadIdx.x;
    if (i >= n4) return;
    float4 v = ((const float4*)in)[i];
    float a[4] = {v.x, v.y, v.z, v.w};
    bf16 h[4], l[4];
    #pragma unroll
    for (int j = 0; j < 4; j++) {
        h[j] = __float2bfloat16(a[j]);
        l[j] = __float2bfloat16(a[j] - __bfloat162float(h[j]));
    }
    *(__nv_bfloat162*)(oh + 4*(size_t)i)     = __halves2bfloat162(h[0], h[1]);
    *(__nv_bfloat162*)(oh + 4*(size_t)i + 2) = __halves2bfloat162(h[2], h[3]);
    *(__nv_bfloat162*)(ol + 4*(size_t)i)     = __halves2bfloat162(l[0], l[1]);
    *(__nv_bfloat162*)(ol + 4*(size_t)i + 2) = __halves2bfloat162(l[2], l[3]);
}

// ---- elementwise / small kernels ----
__global__ void k_zero() { int i = threadIdx.x; if (i < Ee) { g_cnt[i] = 0; g_fill[i] = 0; } }

__global__ void k_rmsnorm(const float* __restrict__ x, const float* __restrict__ w,
                          float* __restrict__ out, bf16* __restrict__ ohi, bf16* __restrict__ olo) {
    int t = blockIdx.x, i = threadIdx.x;
    float4 v = ((const float4*)(x + (size_t)t * Hh))[i];
    __shared__ float red[256];
    red[i] = v.x*v.x + v.y*v.y + v.z*v.z + v.w*v.w;
    __syncthreads();
    for (int s = 128; s > 0; s >>= 1) { if (i < s) red[i] += red[i+s]; __syncthreads(); }
    float rinv = rsqrtf(red[0] * (1.0f / Hh) + 1e-6f);
    float4 wv = ((const float4*)w)[i];
    float4 o = make_float4(v.x*rinv*wv.x, v.y*rinv*wv.y, v.z*rinv*wv.z, v.w*rinv*wv.w);
    ((float4*)(out + (size_t)t * Hh))[i] = o;
    float ov[4] = {o.x, o.y, o.z, o.w};
    bf16 hh[4], ll[4];
    #pragma unroll
    for (int j = 0; j < 4; j++) {
        hh[j] = __float2bfloat16(ov[j]);
        ll[j] = __float2bfloat16(ov[j] - __bfloat162float(hh[j]));
    }
    *(__nv_bfloat162*)(ohi + (size_t)t*Hh + 4*i)     = __halves2bfloat162(hh[0], hh[1]);
    *(__nv_bfloat162*)(ohi + (size_t)t*Hh + 4*i + 2) = __halves2bfloat162(hh[2], hh[3]);
    *(__nv_bfloat162*)(olo + (size_t)t*Hh + 4*i)     = __halves2bfloat162(ll[0], ll[1]);
    *(__nv_bfloat162*)(olo + (size_t)t*Hh + 4*i + 2) = __halves2bfloat162(ll[2], ll[3]);
}

__global__ void k_rope(const float* __restrict__ fc) {
    int idx = blockIdx.x * blockDim.x + threadIdx.x;
    float* X = (blockIdx.y == 0) ? g_q : g_k;
    int j = idx & 31, head = (idx >> 5) & (NHh - 1), t = idx >> 9;
    if (t >= Tt) return;
    int s = t & (Ss - 1);
    float2* p = (float2*)(X + (size_t)t * Hh + head * HDd + 2*j);
    float2 ab = *p;
    float cr = fc[s * HDd + 2*j], ci = fc[s * HDd + 2*j + 1];
    *p = make_float2(ab.x*cr - ab.y*ci, ab.x*ci + ab.y*cr);
}

__device__ __forceinline__ void attn_update(float s, float vx, float vy,
                                            float& m, float& l, float& ax, float& ay) {
    float mn = fmaxf(m, s), sc = __expf(m - mn), p = __expf(s - mn);
    l = l*sc + p; ax = ax*sc + p*vx; ay = ay*sc + p*vy; m = mn;
}

__global__ void k_attn() {
    int gw = (blockIdx.x * blockDim.x + threadIdx.x) >> 5, lane = threadIdx.x & 31;
    if (gw >= Bb * NHh * Ss) return;
    int qi = gw & (Ss - 1), bh = gw >> 10, head = bh & (NHh - 1), b = bh >> 4;
    float2 qv = *(const float2*)(g_q + (size_t)(b*Ss + qi) * Hh + head*HDd + 2*lane);
    qv.x *= 0.125f; qv.y *= 0.125f;
    const float* kb = g_k + ((size_t)b*Ss*Hh + head*HDd + 2*lane);
    const float* vb = g_v + ((size_t)b*Ss*Hh + head*HDd + 2*lane);
    float m = -1e30f, l = 0.f, ax = 0.f, ay = 0.f;
    int nk = qi + 1, j = 0;
    for (; j + 4 <= nk; j += 4) {
        float2 k0 = *(const float2*)(kb + (size_t)(j+0)*Hh), k1 = *(const float2*)(kb + (size_t)(j+1)*Hh);
        float2 k2 = *(const float2*)(kb + (size_t)(j+2)*Hh), k3 = *(const float2*)(kb + (size_t)(j+3)*Hh);
        float s0 = qv.x*k0.x + qv.y*k0.y, s1 = qv.x*k1.x + qv.y*k1.y;
        float s2 = qv.x*k2.x + qv.y*k2.y, s3 = qv.x*k3.x + qv.y*k3.y;
        #pragma unroll
        for (int o = 16; o > 0; o >>= 1) {
            s0 += __shfl_xor_sync(0xffffffffu, s0, o); s1 += __shfl_xor_sync(0xffffffffu, s1, o);
            s2 += __shfl_xor_sync(0xffffffffu, s2, o); s3 += __shfl_xor_sync(0xffffffffu, s3, o);
        }
        float2 v0 = *(const float2*)(vb + (size_t)(j+0)*Hh), v1 = *(const float2*)(vb + (size_t)(j+1)*Hh);
        float2 v2 = *(const float2*)(vb + (size_t)(j+2)*Hh), v3 = *(const float2*)(vb + (size_t)(j+3)*Hh);
        attn_update(s0, v0.x, v0.y, m, l, ax, ay); attn_update(s1, v1.x, v1.y, m, l, ax, ay);
        attn_update(s2, v2.x, v2.y, m, l, ax, ay); attn_update(s3, v3.x, v3.y, m, l, ax, ay);
    }
    for (; j < nk; j++) {
        float2 kv = *(const float2*)(kb + (size_t)j*Hh);
        float s = qv.x*kv.x + qv.y*kv.y;
        #pragma unroll
        for (int o = 16; o > 0; o >>= 1) s += __shfl_xor_sync(0xffffffffu, s, o);
        float2 vv = *(const float2*)(vb + (size_t)j*Hh);
        attn_update(s, vv.x, vv.y, m, l, ax, ay);
    }
    float inv = 1.f / l;
    float ox = ax*inv, oy = ay*inv;
    size_t oo = (size_t)(b*Ss + qi) * Hh + head*HDd + 2*lane;
    bf16 hx = __float2bfloat16(ox), hy = __float2bfloat16(oy);
    *(__nv_bfloat162*)(g_ao_hi + oo) = __halves2bfloat162(hx, hy);
    *(__nv_bfloat162*)(g_ao_lo + oo) = __halves2bfloat162(
        __float2bfloat16(ox - __bfloat162float(hx)), __float2bfloat16(oy - __bfloat162float(hy)));
}

__global__ void k_router(const float* __restrict__ rw) {
    int t = (blockIdx.x * blockDim.x + threadIdx.x) >> 5, lane = threadIdx.x & 31;
    if (t >= Tt) return;
    const float* xr = g_hn + (size_t)t * Hh;
    float acc[Ee] = {};
    for (int hh = lane; hh < Hh; hh += 32) {
        float xv = xr[hh];
        #pragma unroll
        for (int e = 0; e < Ee; e++) acc[e] += xv * rw[hh * Ee + e];
    }
    #pragma unroll
    for (int e = 0; e < Ee; e++)
        #pragma unroll
        for (int o = 16; o > 0; o >>= 1) acc[e] += __shfl_xor_sync(0xffffffffu, acc[e], o);
    if (lane == 0) {
        float mx = acc[0];
        #pragma unroll
        for (int e = 1; e < Ee; e++) mx = fmaxf(mx, acc[e]);
        float p[Ee], s = 0.f;
        #pragma unroll
        for (int e = 0; e < Ee; e++) { p[e] = __expf(acc[e] - mx); s += p[e]; }
        float invs = 1.f / s;
        #pragma unroll
        for (int e = 0; e < Ee; e++) p[e] *= invs;
        int i1 = 0; float v1 = p[0];
        #pragma unroll
        for (int e = 1; e < Ee; e++) if (p[e] > v1) { v1 = p[e]; i1 = e; }
        int i2 = -1; float v2 = -1.f;
        #pragma unroll
        for (int e = 0; e < Ee; e++) if (e != i1 && p[e] > v2) { v2 = p[e]; i2 = e; }
        float inv = 1.f / (v1 + v2);
        g_topi[t*2] = i1; g_topi[t*2+1] = i2;
        g_topw[t*2] = v1 * inv; g_topw[t*2+1] = v2 * inv;
        atomicAdd(&g_cnt[i1], 1); atomicAdd(&g_cnt[i2], 1);
    }
}

__global__ void k_scan() {
    if (threadIdx.x == 0) {
        int o = 0;
        for (int e = 0; e < Ee; e++) { g_off[e] = o; o += g_cnt[e]; g_fill[e] = 0; }
    }
}

__global__ void k_fill() {
    int t = blockIdx.x * blockDim.x + threadIdx.x;
    if (t >= Tt) return;
    for (int kk = 0; kk < 2; kk++) {
        int e = g_topi[t*2 + kk];
        int slot = g_off[e] + atomicAdd(&g_fill[e], 1);
        g_tok[slot] = t; g_slot[t*2 + kk] = slot;
    }
}

__global__ void k_swiglu() {
    size_t i = (size_t)blockIdx.x * blockDim.x + threadIdx.x;
    float2 h1 = ((const float2*)g_t1)[i];
    float2 h3 = ((const float2*)g_t3)[i];
    float a0 = (h1.x / (1.f + __expf(-h1.x))) * h3.x;
    float a1 = (h1.y / (1.f + __expf(-h1.y))) * h3.y;
    bf16 b0 = __float2bfloat16(a0), b1 = __float2bfloat16(a1);
    ((__nv_bfloat162*)g_act_hi)[i] = __halves2bfloat162(b0, b1);
    ((__nv_bfloat162*)g_act_lo)[i] = __halves2bfloat162(
        __float2bfloat16(a0 - __bfloat162float(b0)), __float2bfloat16(a1 - __bfloat162float(b1)));
}

__global__ void k_combine(float* __restrict__ out) {
    int t = blockIdx.x, i = threadIdx.x;
    int s0 = g_slot[t*2], s1 = g_slot[t*2+1];
    float w0 = g_topw[t*2], w1 = g_topw[t*2+1];
    float4 hv = ((const float4*)g_h)[(size_t)t*256 + i];
    float4 y0 = ((const float4*)g_y)[(size_t)s0*256 + i];
    float4 y1 = ((const float4*)g_y)[(size_t)s1*256 + i];
    ((float4*)out)[(size_t)t*256 + i] = make_float4(
        hv.x + w0*y0.x + w1*y1.x, hv.y + w0*y0.y + w1*y1.y,
        hv.z + w0*y0.z + w1*y1.z, hv.w + w0*y0.w + w1*y1.w);
}

// ---------------- launch ----------------
extern "C" void kernel_launch(void* const* d_in, const int* in_sizes, int n_in,
                              void* d_out, int out_size) {
    const float* x   = (const float*)d_in[0];
    const float* anw = (const float*)d_in[1];
    const float* fnw = (const float*)d_in[2];
    const float* wq  = (const float*)d_in[3];
    const float* wk  = (const float*)d_in[4];
    const float* wv  = (const float*)d_in[5];
    const float* wo  = (const float*)d_in[6];
    const float* rw  = (const float*)d_in[7];
    const float* w1  = (const float*)d_in[8];
    const float* w3  = (const float*)d_in[9];
    const float* w2  = (const float*)d_in[10];
    const float* fc  = (const float*)d_in[11];
    float* out = (float*)d_out;

    cudaFuncSetAttribute(k_qkv_mm,  cudaFuncAttributeMaxDynamicSharedMemorySize, SMEM256);
    cudaFuncSetAttribute(k_wo_mm,   cudaFuncAttributeMaxDynamicSharedMemorySize, SMEM128);
    cudaFuncSetAttribute(k_h13_mm,  cudaFuncAttributeMaxDynamicSharedMemorySize, SMEM256);
    cudaFuncSetAttribute(k_moe2_mm, cudaFuncAttributeMaxDynamicSharedMemorySize, SMEM256);

    float *d_xn, *d_h, *d_hn, *d_t1, *d_t3;
    bf16 *d_xnh, *d_xnl, *d_hnh, *d_hnl;
    bf16 *d_qkvh, *d_qkvl, *d_woh, *d_wol, *d_w1h, *d_w1l, *d_w3h, *d_w3l, *d_w2h, *d_w2l;
    cudaGetSymbolAddress((void**)&d_xn, g_xn);   cudaGetSymbolAddress((void**)&d_h, g_h);
    cudaGetSymbolAddress((void**)&d_hn, g_hn);
    cudaGetSymbolAddress((void**)&d_t1, g_t1);   cudaGetSymbolAddress((void**)&d_t3, g_t3);
    cudaGetSymbolAddress((void**)&d_xnh, g_xn_hi); cudaGetSymbolAddress((void**)&d_xnl, g_xn_lo);
    cudaGetSymbolAddress((void**)&d_hnh, g_hn_hi); cudaGetSymbolAddress((void**)&d_hnl, g_hn_lo);
    cudaGetSymbolAddress((void**)&d_qkvh, g_wqkv_hi); cudaGetSymbolAddress((void**)&d_qkvl, g_wqkv_lo);
    cudaGetSymbolAddress((void**)&d_woh, g_wo_hi);    cudaGetSymbolAddress((void**)&d_wol, g_wo_lo);
    cudaGetSymbolAddress((void**)&d_w1h, g_w1_hi);    cudaGetSymbolAddress((void**)&d_w1l, g_w1_lo);
    cudaGetSymbolAddress((void**)&d_w3h, g_w3_hi);    cudaGetSymbolAddress((void**)&d_w3l, g_w3_lo);
    cudaGetSymbolAddress((void**)&d_w2h, g_w2_hi);    cudaGetSymbolAddress((void**)&d_w2l, g_w2_lo);

    k_zero<<<1, 32>>>();
    k_split<<<(Hh*Hh/4)/256, 256>>>(wq, d_qkvh,           d_qkvl,           Hh*Hh/4);
    k_split<<<(Hh*Hh/4)/256, 256>>>(wk, d_qkvh + Hh*Hh,   d_qkvl + Hh*Hh,   Hh*Hh/4);
    k_split<<<(Hh*Hh/4)/256, 256>>>(wv, d_qkvh + 2*Hh*Hh, d_qkvl + 2*Hh*Hh, Hh*Hh/4);
    k_split<<<(Hh*Hh/4)/256, 256>>>(wo, d_woh, d_wol, Hh*Hh/4);
    k_split<<<(Ee*Hh*Ii/4)/256, 256>>>(w1, d_w1h, d_w1l, Ee*Hh*Ii/4);
    k_split<<<(Ee*Hh*Ii/4)/256, 256>>>(w3, d_w3h, d_w3l, Ee*Hh*Ii/4);
    k_split<<<(Ee*Ii*Hh/4)/256, 256>>>(w2, d_w2h, d_w2l, Ee*Ii*Hh/4);

    k_rmsnorm<<<Tt, 256>>>(x, anw, d_xn, d_xnh, d_xnl);
    k_qkv_mm<<<dim3(Hh/256, Tt/128, 3), 256, SMEM256>>>();
    k_rope<<<dim3((Tt * NHh * 32) / 256, 2), 256>>>(fc);
    k_attn<<<(Bb * NHh * Ss) / 4, 128>>>();
    k_wo_mm<<<dim3(Hh/128, Tt/128), 256, SMEM128>>>(x);
    k_rmsnorm<<<Tt, 256>>>(d_h, fnw, d_hn, d_hnh, d_hnl);
    k_router<<<Tt / 8, 256>>>(rw);
    k_scan<<<1, 32>>>();
    k_fill<<<Tt / 256, 256>>>();
    k_h13_mm<<<dim3(Ii/256, Tt/128, Ee), 256, SMEM256>>>(d_w1h, d_w1l, d_t1);
    k_h13_mm<<<dim3(Ii/256, Tt/128, Ee), 256, SMEM256>>>(d_w3h, d_w3l, d_t3);
    k_swiglu<<<(NSLOT * Ii / 2) / 256, 256>>>();
    k_moe2_mm<<<dim3(Hh/256, Tt/128, Ee), 256, SMEM256>>>();
    k_combine<<<Tt, 256>>>(out);
}